// round 3
// baseline (speedup 1.0000x reference)
#include <cuda_runtime.h>

// ---------------------------------------------------------------------------
// FSRGraphConv:
//   acc[dst] += [h[src] | eftr[e]]   (160 feats), cnt[dst] += 1
//   feat_mean = acc / max(cnt,1)
//   out = h_dst @ W1^T + feat_mean @ (weight @ W2^T) + (W_b + bias)
// Fused: scatter (v4 vector REDs) + one 50000x288x128 fp32 GEMM using
// packed fma.rn.f32x2 (2x FFMA throughput, full fp32 precision).
// ---------------------------------------------------------------------------

#define IN_F   128
#define E_F    32
#define FEAT   160
#define OUT_F  128
#define MAX_NODES 50000

__device__ __align__(16) float g_acc[(size_t)MAX_NODES * FEAT];   // 32 MB
__device__ float g_cnt[MAX_NODES];
__device__ __align__(16) float g_Wc[FEAT * OUT_F];    // weight @ W2^T (160x128)
__device__ __align__(16) float g_W1t[IN_F * OUT_F];   // W1t[k][o] = W_w[o][k]

// ---------------------------------------------------------------------------
__global__ void zero_kernel(int n_nodes) {
    size_t tid    = (size_t)blockIdx.x * blockDim.x + threadIdx.x;
    size_t stride = (size_t)gridDim.x * blockDim.x;
    size_t n4 = ((size_t)n_nodes * FEAT) / 4;
    float4* a4 = reinterpret_cast<float4*>(g_acc);
    float4 z = make_float4(0.f, 0.f, 0.f, 0.f);
    for (size_t i = tid; i < n4; i += stride) a4[i] = z;
    for (size_t i = tid; i < (size_t)n_nodes; i += stride) g_cnt[i] = 0.f;
}

__global__ void prep_wc_kernel(const float* __restrict__ weight,
                               const float* __restrict__ W_w) {
    __shared__ float wrow[OUT_F];
    int k = blockIdx.x;
    int o = threadIdx.x;
    wrow[o] = weight[k * OUT_F + o];
    __syncthreads();
    const float* wr = W_w + (size_t)o * (IN_F + OUT_F) + IN_F;
    float s = 0.f;
#pragma unroll 4
    for (int c = 0; c < OUT_F; c++) s = fmaf(wrow[c], wr[c], s);
    g_Wc[k * OUT_F + o] = s;
}

__global__ void prep_w1t_kernel(const float* __restrict__ W_w) {
    int idx = blockIdx.x * blockDim.x + threadIdx.x;
    if (idx < IN_F * OUT_F) {
        int k = idx >> 7;
        int o = idx & 127;
        g_W1t[idx] = W_w[(size_t)o * (IN_F + OUT_F) + k];
    }
}

// ---------------------------------------------------------------------------
__device__ __forceinline__ void red_v4(float* p, float4 v) {
    asm volatile("red.global.add.v4.f32 [%0], {%1, %2, %3, %4};"
                 :: "l"(p), "f"(v.x), "f"(v.y), "f"(v.z), "f"(v.w)
                 : "memory");
}

__global__ void scatter_kernel(const float* __restrict__ h,
                               const float* __restrict__ eftr,
                               const int*   __restrict__ src_idx,
                               const int*   __restrict__ dst_idx,
                               int n_edges) {
    int lane   = threadIdx.x & 31;
    int warp   = (blockIdx.x * blockDim.x + threadIdx.x) >> 5;
    int nwarps = (gridDim.x * blockDim.x) >> 5;

    for (int e = warp; e < n_edges; e += nwarps) {
        int s = src_idx[e];
        int d = dst_idx[e];
        float4 v = reinterpret_cast<const float4*>(h + (size_t)s * IN_F)[lane];
        float* arow = g_acc + (size_t)d * FEAT;
        red_v4(arow + lane * 4, v);
        if (lane < 8) {
            float4 ev = reinterpret_cast<const float4*>(eftr + (size_t)e * E_F)[lane];
            red_v4(arow + IN_F + lane * 4, ev);
        }
        if (lane == 0) atomicAdd(&g_cnt[d], 1.0f);
    }
}

// ---------------------------------------------------------------------------
// packed fp32x2 helpers
__device__ __forceinline__ unsigned long long ffma2(unsigned long long a,
                                                    unsigned long long b,
                                                    unsigned long long c) {
    unsigned long long d;
    asm("fma.rn.f32x2 %0, %1, %2, %3;" : "=l"(d) : "l"(a), "l"(b), "l"(c));
    return d;
}
__device__ __forceinline__ unsigned long long pack2(float lo, float hi) {
    unsigned long long d;
    asm("mov.b64 %0, {%1, %2};" : "=l"(d) : "f"(lo), "f"(hi));
    return d;
}
__device__ __forceinline__ float2 unpack2(unsigned long long v) {
    float lo, hi;
    asm("mov.b64 {%0, %1}, %2;" : "=f"(lo), "=f"(hi) : "l"(v));
    return make_float2(lo, hi);
}

// fused GEMM: out = [h_dst | acc/den] @ [W1t; Wc] + (W_b + bias)
// BM=128, BN=128, BK=16 (18 chunks). 256 threads, 8x8/thread via fp32x2.
#define BM 128
#define BN 128
#define BK 16

__global__ void gemm_kernel(const float* __restrict__ h,
                            const float* __restrict__ W_b,
                            const float* __restrict__ bias,
                            float* __restrict__ out,
                            int n_nodes) {
    __shared__ float Xs[BK][BM + 4];
    __shared__ __align__(16) float Ws[BK][BN];
    __shared__ float sden[BM];

    int m0 = blockIdx.x * BM;
    int t  = threadIdx.x;
    int tx = t & 15;
    int ty = t >> 4;

    if (t < BM) {
        int node = m0 + t;
        float c = (node < n_nodes) ? g_cnt[node] : 1.f;
        sden[t] = 1.f / fmaxf(c, 1.f);
    }
    __syncthreads();

    // 8 rows x 4 packed-column-pairs of fp32x2 accumulators (= 8x8 floats)
    unsigned long long acc2[8][4];
#pragma unroll
    for (int i = 0; i < 8; i++)
#pragma unroll
        for (int j = 0; j < 4; j++) acc2[i][j] = 0ull;

    for (int kc = 0; kc < 18; kc++) {
        // --- X tile (128 x 16), stored k-major ---
#pragma unroll
        for (int i = 0; i < 2; i++) {
            int idx = t + i * 256;
            int m   = idx >> 2;
            int k4  = idx & 3;
            int node = m0 + m;
            float4 v = make_float4(0.f, 0.f, 0.f, 0.f);
            if (node < n_nodes) {
                if (kc < 8) {
                    v = *reinterpret_cast<const float4*>(
                            h + (size_t)node * IN_F + kc * BK + k4 * 4);
                } else {
                    v = *reinterpret_cast<const float4*>(
                            g_acc + (size_t)node * FEAT + (kc - 8) * BK + k4 * 4);
                    float dn = sden[m];
                    v.x *= dn; v.y *= dn; v.z *= dn; v.w *= dn;
                }
            }
            Xs[k4 * 4 + 0][m] = v.x;
            Xs[k4 * 4 + 1][m] = v.y;
            Xs[k4 * 4 + 2][m] = v.z;
            Xs[k4 * 4 + 3][m] = v.w;
        }
        // --- W tile (16 x 128) ---
        const float* Wsrc = (kc < 8) ? (g_W1t + kc * BK * OUT_F)
                                     : (g_Wc + (kc - 8) * BK * OUT_F);
#pragma unroll
        for (int i = 0; i < 2; i++) {
            int idx = t + i * 256;
            int k   = idx >> 5;
            int n4  = idx & 31;
            *reinterpret_cast<float4*>(&Ws[k][n4 * 4]) =
                *reinterpret_cast<const float4*>(Wsrc + k * OUT_F + n4 * 4);
        }
        __syncthreads();

#pragma unroll
        for (int kk = 0; kk < BK; kk++) {
            float4 x0 = *reinterpret_cast<const float4*>(&Xs[kk][ty * 8]);
            float4 x1 = *reinterpret_cast<const float4*>(&Xs[kk][ty * 8 + 4]);
            // W row as 4 packed pairs (16B-aligned)
            const unsigned long long* wrow =
                reinterpret_cast<const unsigned long long*>(&Ws[kk][tx * 8]);
            unsigned long long w01 = wrow[0];
            unsigned long long w23 = wrow[1];
            unsigned long long w45 = wrow[2];
            unsigned long long w67 = wrow[3];

            float xv[8] = {x0.x, x0.y, x0.z, x0.w, x1.x, x1.y, x1.z, x1.w};
#pragma unroll
            for (int i = 0; i < 8; i++) {
                unsigned long long xx = pack2(xv[i], xv[i]);
                acc2[i][0] = ffma2(xx, w01, acc2[i][0]);
                acc2[i][1] = ffma2(xx, w23, acc2[i][1]);
                acc2[i][2] = ffma2(xx, w45, acc2[i][2]);
                acc2[i][3] = ffma2(xx, w67, acc2[i][3]);
            }
        }
        __syncthreads();
    }

    // epilogue
    float bv[8];
#pragma unroll
    for (int j = 0; j < 8; j++) {
        int o = tx * 8 + j;
        bv[j] = W_b[o] + bias[o];
    }
#pragma unroll
    for (int i = 0; i < 8; i++) {
        int node = m0 + ty * 8 + i;
        if (node < n_nodes) {
            float* orow = out + (size_t)node * OUT_F + tx * 8;
            float2 a01 = unpack2(acc2[i][0]);
            float2 a23 = unpack2(acc2[i][1]);
            float2 a45 = unpack2(acc2[i][2]);
            float2 a67 = unpack2(acc2[i][3]);
            float4 r0 = make_float4(a01.x + bv[0], a01.y + bv[1],
                                    a23.x + bv[2], a23.y + bv[3]);
            float4 r1 = make_float4(a45.x + bv[4], a45.y + bv[5],
                                    a67.x + bv[6], a67.y + bv[7]);
            *reinterpret_cast<float4*>(orow)     = r0;
            *reinterpret_cast<float4*>(orow + 4) = r1;
        }
    }
}

// ---------------------------------------------------------------------------
extern "C" void kernel_launch(void* const* d_in, const int* in_sizes, int n_in,
                              void* d_out, int out_size) {
    const float* h      = (const float*)d_in[0];
    const float* eftr   = (const float*)d_in[1];
    const float* weight = (const float*)d_in[2];
    const float* W_w    = (const float*)d_in[3];
    const float* W_b    = (const float*)d_in[4];
    const float* bias   = (const float*)d_in[5];
    const int*   src    = (const int*)d_in[6];
    const int*   dst    = (const int*)d_in[7];
    float* out = (float*)d_out;

    int n_nodes = in_sizes[0] / IN_F;
    int n_edges = in_sizes[7];

    zero_kernel<<<1024, 256>>>(n_nodes);
    prep_wc_kernel<<<FEAT, OUT_F>>>(weight, W_w);
    prep_w1t_kernel<<<(IN_F * OUT_F + 255) / 256, 256>>>(W_w);
    scatter_kernel<<<2048, 256>>>(h, eftr, src, dst, n_edges);
    gemm_kernel<<<(n_nodes + BM - 1) / BM, 256>>>(h, W_b, bias, out, n_nodes);
}